// round 4
// baseline (speedup 1.0000x reference)
#include <cuda_runtime.h>
#include <cuda_bf16.h>

#define Nn 1024
#define Mm 256
#define Bb 1024
#define Kk (Nn + Mm)   // 1280 fused K
#define BM 64
#define BN 64
#define BK 16
#define BETA 0.01f
#define EPSL 1e-12f

// z = softthresh(W1 @ x + W2 @ y), W1[n,k] = v[N-1+n-k] (Toeplitz, on the fly)
// omode 0: out is bf16, interleaved (re,im) pairs -> 2*N*B bf16 elements
// omode 1: out is fp32, real part only            -> N*B float elements
__global__ __launch_bounds__(256)
void fused_toeplitz_gemm_kernel(
    const float* __restrict__ v_re,  const float* __restrict__ v_im,
    const float* __restrict__ W2_re, const float* __restrict__ W2_im,
    const float* __restrict__ x_re,  const float* __restrict__ x_im,
    const float* __restrict__ y_re,  const float* __restrict__ y_im,
    void* __restrict__ out, int omode)
{
    __shared__ __align__(16) float As_re[BK][BM];
    __shared__ __align__(16) float As_im[BK][BM];
    __shared__ __align__(16) float Bs_re[BK][BN];
    __shared__ __align__(16) float Bs_im[BK][BN];

    const int t  = threadIdx.x;
    const int tx = t & 15;      // column group (b)
    const int ty = t >> 4;      // row group (n)
    const int row0 = blockIdx.y * BM;
    const int col0 = blockIdx.x * BN;

    float acc_re[4][4] = {};
    float acc_im[4][4] = {};

    for (int kt = 0; kt < Kk / BK; ++kt) {
        const int k0 = kt * BK;

        // ---- stage A tile (64 rows x 16 k), re/im planes ----
        if (k0 < Nn) {
            #pragma unroll
            for (int i = 0; i < 4; ++i) {
                int idx = t + i * 256;
                int nl = idx & 63;
                int kl = idx >> 6;
                int g  = (Nn - 1) + (row0 + nl) - (k0 + kl);
                As_re[kl][nl] = v_re[g];
                As_im[kl][nl] = v_im[g];
            }
        } else {
            #pragma unroll
            for (int i = 0; i < 4; ++i) {
                int idx = t + i * 256;
                int kl = idx & 15;
                int nl = idx >> 4;
                int g  = (row0 + nl) * Mm + (k0 - Nn + kl);
                As_re[kl][nl] = W2_re[g];
                As_im[kl][nl] = W2_im[g];
            }
        }

        // ---- stage B tile (16 k x 64 cols): x for k<N, y for k>=N ----
        const float* src_re = (k0 < Nn) ? x_re : y_re;
        const float* src_im = (k0 < Nn) ? x_im : y_im;
        const int kbase = (k0 < Nn) ? k0 : (k0 - Nn);
        #pragma unroll
        for (int i = 0; i < 4; ++i) {
            int idx = t + i * 256;
            int cl = idx & 63;
            int kl = idx >> 6;
            int g  = (kbase + kl) * Bb + (col0 + cl);
            Bs_re[kl][cl] = src_re[g];
            Bs_im[kl][cl] = src_im[g];
        }
        __syncthreads();

        // ---- 4x4 complex FMA microkernel ----
        #pragma unroll
        for (int kk = 0; kk < BK; ++kk) {
            float4 ar4 = *(const float4*)&As_re[kk][ty * 4];
            float4 ai4 = *(const float4*)&As_im[kk][ty * 4];
            float4 br4 = *(const float4*)&Bs_re[kk][tx * 4];
            float4 bi4 = *(const float4*)&Bs_im[kk][tx * 4];
            float arv[4] = {ar4.x, ar4.y, ar4.z, ar4.w};
            float aiv[4] = {ai4.x, ai4.y, ai4.z, ai4.w};
            float brv[4] = {br4.x, br4.y, br4.z, br4.w};
            float biv[4] = {bi4.x, bi4.y, bi4.z, bi4.w};
            #pragma unroll
            for (int i = 0; i < 4; ++i) {
                #pragma unroll
                for (int j = 0; j < 4; ++j) {
                    acc_re[i][j] = fmaf(arv[i], brv[j], acc_re[i][j]);
                    acc_re[i][j] = fmaf(-aiv[i], biv[j], acc_re[i][j]);
                    acc_im[i][j] = fmaf(arv[i], biv[j], acc_im[i][j]);
                    acc_im[i][j] = fmaf(aiv[i], brv[j], acc_im[i][j]);
                }
            }
        }
        __syncthreads();
    }

    // ---- epilogue: complex soft-threshold ----
    #pragma unroll
    for (int i = 0; i < 4; ++i) {
        const int row = row0 + ty * 4 + i;
        #pragma unroll
        for (int j = 0; j < 4; ++j) {
            const int col = col0 + tx * 4 + j;
            float re = acc_re[i][j];
            float im = acc_im[i][j];
            float mag = sqrtf(re * re + im * im);
            float scale = fmaxf(mag - BETA, 0.0f) / fmaxf(mag, EPSL);
            re *= scale;
            im *= scale;
            const int e = row * Bb + col;
            if (omode == 0) {
                // bf16 interleaved pairs: exactly 2*N*B bf16 = 4MB total
                __nv_bfloat162 p;
                p.x = __float2bfloat16_rn(re);
                p.y = __float2bfloat16_rn(im);
                ((__nv_bfloat162*)out)[e] = p;
            } else {
                // fp32 real part only: exactly N*B floats = 4MB total
                ((float*)out)[e] = re;
            }
        }
    }
}

extern "C" void kernel_launch(void* const* d_in, const int* in_sizes, int n_in,
                              void* d_out, int out_size) {
    // Crash-proof input dispatch: classify strictly by element count.
    // Handles in_sizes in elements (v=2047) or bytes (v=8188).
    int scale = 1;
    bool have2047 = false, have8188 = false;
    for (int i = 0; i < n_in && i < 8; ++i) {
        if (in_sizes[i] == 2 * Nn - 1) have2047 = true;
        if (in_sizes[i] == (2 * Nn - 1) * 4) have8188 = true;
    }
    if (!have2047 && have8188) scale = 4;

    const float* vp[2] = {0, 0};
    const float* xp[2] = {0, 0};
    const float* mp[4] = {0, 0, 0, 0};
    int nv = 0, nx = 0, nm = 0;
    for (int i = 0; i < n_in && i < 8; ++i) {
        const float* p = (const float*)d_in[i];
        long s = in_sizes[i];
        if (s == (long)(2 * Nn - 1) * scale)      { if (nv < 2) vp[nv++] = p; }
        else if (s == (long)Nn * Bb * scale)      { if (nx < 2) xp[nx++] = p; }
        else if (s == (long)Nn * Mm * scale)      { if (nm < 4) mp[nm++] = p; }
    }
    // Fallback to metadata/dict order if classification failed.
    const float* v_re  = vp[0] ? vp[0] : (const float*)d_in[0];
    const float* v_im  = vp[1] ? vp[1] : (const float*)d_in[1];
    const float* W2_re = mp[0] ? mp[0] : (const float*)d_in[2];
    const float* W2_im = mp[1] ? mp[1] : (const float*)d_in[3];
    const float* x_re  = xp[0] ? xp[0] : (const float*)d_in[4];
    const float* x_im  = xp[1] ? xp[1] : (const float*)d_in[5];
    const float* y_re  = mp[2] ? mp[2] : (const float*)d_in[6];
    const float* y_im  = mp[3] ? mp[3] : (const float*)d_in[7];

    // Output mode: out_size >= 2*N*B -> bf16 interleaved (writes out_size*2 B);
    // otherwise fp32 real-only (writes out_size*4 B; also fits complex64 buffer).
    const int omode = (out_size >= 2 * Nn * Bb) ? 0 : 1;

    dim3 grid(Bb / BN, Nn / BM);   // (16, 16)
    dim3 block(256);
    fused_toeplitz_gemm_kernel<<<grid, block>>>(
        v_re, v_im, W2_re, W2_im, x_re, x_im, y_re, y_im,
        d_out, omode);
}

// round 5
// speedup vs baseline: 1.1963x; 1.1963x over previous
#include <cuda_runtime.h>
#include <cuda_bf16.h>

#define Nn 1024
#define Mm 256
#define Bb 1024
#define Kk (Nn + Mm)   // 1280 fused K
#define BM 64
#define BN 64
#define BK 16
#define NT (Kk / BK)   // 80 k-tiles
#define BETA 0.01f
#define EPSL 1e-12f

typedef unsigned long long u64;

__device__ __forceinline__ u64 splat2(float x) {
    u64 r; asm("mov.b64 %0, {%1, %1};" : "=l"(r) : "f"(x)); return r;
}
__device__ __forceinline__ u64 ffma2(u64 a, u64 b, u64 c) {
    u64 d; asm("fma.rn.f32x2 %0, %1, %2, %3;" : "=l"(d) : "l"(a), "l"(b), "l"(c)); return d;
}
__device__ __forceinline__ void unpk2(u64 p, float& lo, float& hi) {
    asm("mov.b64 {%0, %1}, %2;" : "=f"(lo), "=f"(hi) : "l"(p));
}

// z = softthresh(W1 @ x + W2 @ y), W1[n,k] = v[N-1+n-k] (Toeplitz, on the fly)
// omode 0: out is bf16 interleaved (re,im) -> 2*N*B bf16 elements
// omode 1: out is fp32 real part only     -> N*B float elements
__global__ __launch_bounds__(256, 2)
void fused_toeplitz_gemm_f32x2_kernel(
    const float* __restrict__ v_re,  const float* __restrict__ v_im,
    const float* __restrict__ W2_re, const float* __restrict__ W2_im,
    const float* __restrict__ x_re,  const float* __restrict__ x_im,
    const float* __restrict__ y_re,  const float* __restrict__ y_im,
    void* __restrict__ out, int omode)
{
    __shared__ __align__(16) float As_re[2][BK][BM];
    __shared__ __align__(16) float As_im[2][BK][BM];
    __shared__ __align__(16) float Bs_re[2][BK][BN];
    __shared__ __align__(16) float Bs_im[2][BK][BN];

    const int t  = threadIdx.x;
    const int tx = t & 15;      // column group (b): 4 cols = 2 packed pairs
    const int ty = t >> 4;      // row group (n):    4 rows
    const int row0 = blockIdx.y * BM;
    const int col0 = blockIdx.x * BN;

    // Packed accumulators: acc over j-pairs. re = rr - ii at epilogue.
    u64 acc_rr[4][2] = {};
    u64 acc_ii[4][2] = {};
    u64 acc_im[4][2] = {};

    // Per-thread staging registers (A tile: 4 entries, B tile: 4 entries).
    float Ar[4], Ai[4], Br[4], Bi[4];
    // Precomputed staging coordinates (constant across kt).
    int a_nl[4], a_kl[4], b_cl[4], b_kl[4];
    #pragma unroll
    for (int i = 0; i < 4; ++i) {
        int idx = t + i * 256;
        a_nl[i] = idx & 63; a_kl[i] = idx >> 6;   // Toeplitz layout (n-contig)
        b_cl[i] = idx & 63; b_kl[i] = idx >> 6;
    }

    // ---- load tile kt into regs ----
    auto load_regs = [&](int kt) {
        const int k0 = kt * BK;
        if (k0 < Nn) {
            #pragma unroll
            for (int i = 0; i < 4; ++i) {
                int g = (Nn - 1) + (row0 + a_nl[i]) - (k0 + a_kl[i]);
                Ar[i] = v_re[g];
                Ai[i] = v_im[g];
            }
            #pragma unroll
            for (int i = 0; i < 4; ++i) {
                int g = (k0 + b_kl[i]) * Bb + (col0 + b_cl[i]);
                Br[i] = x_re[g];
                Bi[i] = x_im[g];
            }
        } else {
            #pragma unroll
            for (int i = 0; i < 4; ++i) {
                int idx = t + i * 256;
                int kl = idx & 15, nl = idx >> 4;   // k-contig for coalesced W2 rows
                int g = (row0 + nl) * Mm + (k0 - Nn + kl);
                Ar[i] = W2_re[g];
                Ai[i] = W2_im[g];
            }
            #pragma unroll
            for (int i = 0; i < 4; ++i) {
                int g = (k0 - Nn + b_kl[i]) * Bb + (col0 + b_cl[i]);
                Br[i] = y_re[g];
                Bi[i] = y_im[g];
            }
        }
    };

    // ---- store staged regs into smem buffer bf ----
    auto store_smem = [&](int bf, int kt) {
        const int k0 = kt * BK;
        if (k0 < Nn) {
            #pragma unroll
            for (int i = 0; i < 4; ++i) {
                As_re[bf][a_kl[i]][a_nl[i]] = Ar[i];
                As_im[bf][a_kl[i]][a_nl[i]] = Ai[i];
            }
        } else {
            #pragma unroll
            for (int i = 0; i < 4; ++i) {
                int idx = t + i * 256;
                int kl = idx & 15, nl = idx >> 4;
                As_re[bf][kl][nl] = Ar[i];
                As_im[bf][kl][nl] = Ai[i];
            }
        }
        #pragma unroll
        for (int i = 0; i < 4; ++i) {
            Bs_re[bf][b_kl[i]][b_cl[i]] = Br[i];
            Bs_im[bf][b_kl[i]][b_cl[i]] = Bi[i];
        }
    };

    // prologue: stage tile 0 into buffer 0
    load_regs(0);
    store_smem(0, 0);
    __syncthreads();

    #pragma unroll 2
    for (int kt = 0; kt < NT; ++kt) {
        const int buf = kt & 1;
        // issue next tile's global loads first (latency hidden by compute)
        if (kt + 1 < NT) load_regs(kt + 1);

        // ---- packed 4x(2x2) complex FFMA2 microkernel ----
        #pragma unroll
        for (int kk = 0; kk < BK; ++kk) {
            const float4 ar4 = *(const float4*)&As_re[buf][kk][ty * 4];
            const float4 ai4 = *(const float4*)&As_im[buf][kk][ty * 4];
            const ulonglong2 br = *(const ulonglong2*)&Bs_re[buf][kk][tx * 4];
            const ulonglong2 bi = *(const ulonglong2*)&Bs_im[buf][kk][tx * 4];
            const float arv[4] = {ar4.x, ar4.y, ar4.z, ar4.w};
            const float aiv[4] = {ai4.x, ai4.y, ai4.z, ai4.w};
            #pragma unroll
            for (int i = 0; i < 4; ++i) {
                const u64 a2 = splat2(arv[i]);
                const u64 c2 = splat2(aiv[i]);
                acc_rr[i][0] = ffma2(a2, br.x, acc_rr[i][0]);
                acc_rr[i][1] = ffma2(a2, br.y, acc_rr[i][1]);
                acc_ii[i][0] = ffma2(c2, bi.x, acc_ii[i][0]);
                acc_ii[i][1] = ffma2(c2, bi.y, acc_ii[i][1]);
                acc_im[i][0] = ffma2(a2, bi.x, acc_im[i][0]);
                acc_im[i][1] = ffma2(a2, bi.y, acc_im[i][1]);
                acc_im[i][0] = ffma2(c2, br.x, acc_im[i][0]);
                acc_im[i][1] = ffma2(c2, br.y, acc_im[i][1]);
            }
        }

        // store next tile into the other buffer (its old readers synced last iter)
        if (kt + 1 < NT) store_smem(buf ^ 1, kt + 1);
        __syncthreads();
    }

    // ---- epilogue: re = rr - ii, complex soft-threshold ----
    #pragma unroll
    for (int i = 0; i < 4; ++i) {
        const int row = row0 + ty * 4 + i;
        #pragma unroll
        for (int p = 0; p < 2; ++p) {
            float rr0, rr1, ii0, ii1, im0, im1;
            unpk2(acc_rr[i][p], rr0, rr1);
            unpk2(acc_ii[i][p], ii0, ii1);
            unpk2(acc_im[i][p], im0, im1);
            float rev[2] = {rr0 - ii0, rr1 - ii1};
            float imv[2] = {im0, im1};
            #pragma unroll
            for (int l = 0; l < 2; ++l) {
                const int col = col0 + tx * 4 + p * 2 + l;
                float re = rev[l];
                float im = imv[l];
                float mag = sqrtf(re * re + im * im);
                float scale = fmaxf(mag - BETA, 0.0f) / fmaxf(mag, EPSL);
                re *= scale;
                im *= scale;
                const int e = row * Bb + col;
                if (omode == 0) {
                    __nv_bfloat162 pb;
                    pb.x = __float2bfloat16_rn(re);
                    pb.y = __float2bfloat16_rn(im);
                    ((__nv_bfloat162*)out)[e] = pb;
                } else {
                    ((float*)out)[e] = re;
                }
            }
        }
    }
}

extern "C" void kernel_launch(void* const* d_in, const int* in_sizes, int n_in,
                              void* d_out, int out_size) {
    // Crash-proof input dispatch: classify strictly by element count.
    // Handles in_sizes in elements (v=2047) or bytes (v=8188).
    int scale = 1;
    bool have2047 = false, have8188 = false;
    for (int i = 0; i < n_in && i < 8; ++i) {
        if (in_sizes[i] == 2 * Nn - 1) have2047 = true;
        if (in_sizes[i] == (2 * Nn - 1) * 4) have8188 = true;
    }
    if (!have2047 && have8188) scale = 4;

    const float* vp[2] = {0, 0};
    const float* xp[2] = {0, 0};
    const float* mp[4] = {0, 0, 0, 0};
    int nv = 0, nx = 0, nm = 0;
    for (int i = 0; i < n_in && i < 8; ++i) {
        const float* p = (const float*)d_in[i];
        long s = in_sizes[i];
        if (s == (long)(2 * Nn - 1) * scale)      { if (nv < 2) vp[nv++] = p; }
        else if (s == (long)Nn * Bb * scale)      { if (nx < 2) xp[nx++] = p; }
        else if (s == (long)Nn * Mm * scale)      { if (nm < 4) mp[nm++] = p; }
    }
    // Fallback to metadata/dict order if classification failed.
    const float* v_re  = vp[0] ? vp[0] : (const float*)d_in[0];
    const float* v_im  = vp[1] ? vp[1] : (const float*)d_in[1];
    const float* W2_re = mp[0] ? mp[0] : (const float*)d_in[2];
    const float* W2_im = mp[1] ? mp[1] : (const float*)d_in[3];
    const float* x_re  = xp[0] ? xp[0] : (const float*)d_in[4];
    const float* x_im  = xp[1] ? xp[1] : (const float*)d_in[5];
    const float* y_re  = mp[2] ? mp[2] : (const float*)d_in[6];
    const float* y_im  = mp[3] ? mp[3] : (const float*)d_in[7];

    // Output mode: out_size >= 2*N*B -> bf16 interleaved (writes out_size*2 B);
    // otherwise fp32 real-only (writes out_size*4 B; also fits complex64 buffer).
    const int omode = (out_size >= 2 * Nn * Bb) ? 0 : 1;

    dim3 grid(Bb / BN, Nn / BM);   // (16, 16)
    dim3 block(256);
    fused_toeplitz_gemm_f32x2_kernel<<<grid, block>>>(
        v_re, v_im, W2_re, W2_im, x_re, x_im, y_re, y_im,
        d_out, omode);
}

// round 7
// speedup vs baseline: 2.6155x; 2.1863x over previous
#include <cuda_runtime.h>
#include <cuda_bf16.h>
#include <cstdint>
#include <cstring>

#define Nn 1024
#define Mm 256
#define Bb 1024
#define Kk (Nn + Mm)      // 1280
#define TMt 128           // CTA tile rows
#define TNt 64            // CTA tile cols
#define TKt 32            // K per staged tile
#define NTIL (Kk / TKt)   // 40
#define BETA 0.01f
#define EPSL 1e-12f
#define THREADS 256

typedef uint32_t u32;

// smem plane layout: bf16 [rows][40] (80B padded rows -> conflict-free frag LDS)
#define APL (128 * 80)               // A plane bytes
#define BPL (64 * 80)                // B plane bytes
#define BUFSZ (6 * APL + 6 * BPL)    // Arh,Arl,Aih,Ail,Ash,Asl | Brh,Brl,Bih,Bil,Bsh,Bsl
#define SMTOT (2 * BUFSZ)            // 184320 B dynamic

static __device__ __forceinline__ void hilo(float a, float b, u32& h, u32& l) {
    __nv_bfloat162 t = __floats2bfloat162_rn(a, b);
    u32 hu; memcpy(&hu, &t, 4);
    h = hu;
    float fa = __uint_as_float(hu << 16);
    float fb = __uint_as_float(hu & 0xFFFF0000u);
    __nv_bfloat162 t2 = __floats2bfloat162_rn(a - fa, b - fb);
    memcpy(&l, &t2, 4);
}
static __device__ __forceinline__ void mma16816(float* c, const u32* a, const u32* b) {
    asm volatile(
        "mma.sync.aligned.m16n8k16.row.col.f32.bf16.bf16.f32 "
        "{%0,%1,%2,%3}, {%4,%5,%6,%7}, {%8,%9}, {%0,%1,%2,%3};"
        : "+f"(c[0]), "+f"(c[1]), "+f"(c[2]), "+f"(c[3])
        : "r"(a[0]), "r"(a[1]), "r"(a[2]), "r"(a[3]), "r"(b[0]), "r"(b[1]));
}

// z = softthresh(W1 @ x + W2 @ y); W1[n,k]=v[N-1+n-k].
// Split-2 bf16 + Gauss 3-product complex GEMM on mma.sync (baseline HMMA).
__global__ __launch_bounds__(THREADS, 1)
void toeplitz_hmma_kernel(
    const float* __restrict__ v_re,  const float* __restrict__ v_im,
    const float* __restrict__ W2_re, const float* __restrict__ W2_im,
    const float* __restrict__ x_re,  const float* __restrict__ x_im,
    const float* __restrict__ y_re,  const float* __restrict__ y_im,
    void* __restrict__ out, int omode)
{
    extern __shared__ char smem[];
    const int tid = threadIdx.x;
    const int wid = tid >> 5;
    const int lid = tid & 31;
    const int wr = wid >> 1, wc = wid & 1;      // 4x2 warp grid
    const int wm = wr * 32, wn = wc * 32;      // warp tile 32x32
    const int r4 = lid >> 2;
    const int c2 = (lid & 3) * 2;
    const int row0 = blockIdx.y * TMt;
    const int col0 = blockIdx.x * TNt;

    // acc[plane][mt][nt][4]; planes: 0=P1(ar*br), 1=P2(ai*bi), 2=P3(as*bs)
    float acc[3][2][4][4];
    #pragma unroll
    for (int p = 0; p < 3; ++p)
        #pragma unroll
        for (int mt = 0; mt < 2; ++mt)
            #pragma unroll
            for (int nt = 0; nt < 4; ++nt)
                #pragma unroll
                for (int q = 0; q < 4; ++q) acc[p][mt][nt][q] = 0.0f;

    // staging regs
    float Ar0[8], Ar1[8], Ai0[8], Ai1[8];
    float Br0[4], Br1[4], Bi0[4], Bi1[4];

    auto load_regs = [&](int t) {
        const int k0 = t * TKt;
        if (k0 < Nn) {
            #pragma unroll
            for (int it = 0; it < 8; ++it) {
                int idx = tid + it * THREADS;      // 0..2047
                int kp = idx & 15, n = idx >> 4;   // k = 2*kp
                int g = 1023 + (row0 + n) - (k0 + 2 * kp);
                Ar0[it] = v_re[g]; Ar1[it] = v_re[g - 1];
                Ai0[it] = v_im[g]; Ai1[it] = v_im[g - 1];
            }
        } else {
            #pragma unroll
            for (int it = 0; it < 8; ++it) {
                int idx = tid + it * THREADS;
                int kp = idx & 15, n = idx >> 4;
                int g = (row0 + n) * Mm + (k0 - Nn + 2 * kp);
                Ar0[it] = W2_re[g]; Ar1[it] = W2_re[g + 1];
                Ai0[it] = W2_im[g]; Ai1[it] = W2_im[g + 1];
            }
        }
        const float* sr = (k0 < Nn) ? x_re : y_re;
        const float* si = (k0 < Nn) ? x_im : y_im;
        const int kb = (k0 < Nn) ? k0 : (k0 - Nn);
        #pragma unroll
        for (int it = 0; it < 4; ++it) {
            int idx = tid + it * THREADS;          // 0..1023
            int cc = idx & 63, kp = idx >> 6;      // k = 2*kp
            int g = (kb + 2 * kp) * Bb + col0 + cc;
            Br0[it] = sr[g]; Br1[it] = sr[g + Bb];
            Bi0[it] = si[g]; Bi1[it] = si[g + Bb];
        }
    };

    auto store_smem = [&](int bf) {
        char* base = smem + bf * BUFSZ;
        char* Arh = base;            char* Arl = base + APL;
        char* Aih = base + 2 * APL;  char* Ail = base + 3 * APL;
        char* Ash = base + 4 * APL;  char* Asl = base + 5 * APL;
        char* Bh0 = base + 6 * APL;
        #pragma unroll
        for (int it = 0; it < 8; ++it) {
            int idx = tid + it * THREADS;
            int kp = idx & 15, n = idx >> 4;
            u32 off = (u32)(n * 80 + kp * 4);
            u32 h, l;
            hilo(Ar0[it], Ar1[it], h, l);
            *(u32*)(Arh + off) = h; *(u32*)(Arl + off) = l;
            hilo(Ai0[it], Ai1[it], h, l);
            *(u32*)(Aih + off) = h; *(u32*)(Ail + off) = l;
            hilo(Ar0[it] + Ai0[it], Ar1[it] + Ai1[it], h, l);
            *(u32*)(Ash + off) = h; *(u32*)(Asl + off) = l;
        }
        #pragma unroll
        for (int it = 0; it < 4; ++it) {
            int idx = tid + it * THREADS;
            int cc = idx & 63, kp = idx >> 6;
            u32 off = (u32)(cc * 80 + kp * 4);
            u32 h, l;
            hilo(Br0[it], Br1[it], h, l);
            *(u32*)(Bh0 + off) = h; *(u32*)(Bh0 + BPL + off) = l;
            hilo(Bi0[it], Bi1[it], h, l);
            *(u32*)(Bh0 + 2 * BPL + off) = h; *(u32*)(Bh0 + 3 * BPL + off) = l;
            hilo(Br0[it] + Bi0[it], Br1[it] + Bi1[it], h, l);
            *(u32*)(Bh0 + 4 * BPL + off) = h; *(u32*)(Bh0 + 5 * BPL + off) = l;
        }
    };

    load_regs(0);
    store_smem(0);
    __syncthreads();

    for (int t = 0; t < NTIL; ++t) {
        const int buf = t & 1;
        if (t + 1 < NTIL) load_regs(t + 1);

        char* base = smem + buf * BUFSZ;
        #pragma unroll
        for (int ks = 0; ks < 2; ++ks) {
            const u32 kbB = (u32)(ks * 32);   // 16 k * 2B
            #pragma unroll
            for (int p = 0; p < 3; ++p) {
                char* Ah = base + (2 * p) * APL;
                char* Al = Ah + APL;
                char* Bh = base + 6 * APL + (2 * p) * BPL;
                char* Bl = Bh + BPL;
                u32 ah[2][4], al[2][4], bh[4][2], bl[4][2];
                #pragma unroll
                for (int mt = 0; mt < 2; ++mt) {
                    u32 o = (u32)((wm + mt * 16 + r4) * 80) + kbB + (u32)(c2 * 2);
                    ah[mt][0] = *(u32*)(Ah + o);
                    ah[mt][1] = *(u32*)(Ah + o + 8 * 80);
                    ah[mt][2] = *(u32*)(Ah + o + 16);
                    ah[mt][3] = *(u32*)(Ah + o + 8 * 80 + 16);
                    al[mt][0] = *(u32*)(Al + o);
                    al[mt][1] = *(u32*)(Al + o + 8 * 80);
                    al[mt][2] = *(u32*)(Al + o + 16);
                    al[mt][3] = *(u32*)(Al + o + 8 * 80 + 16);
                }
                #pragma unroll
                for (int nt = 0; nt < 4; ++nt) {
                    u32 o = (u32)((wn + nt * 8 + r4) * 80) + kbB + (u32)(c2 * 2);
                    bh[nt][0] = *(u32*)(Bh + o);
                    bh[nt][1] = *(u32*)(Bh + o + 16);
                    bl[nt][0] = *(u32*)(Bl + o);
                    bl[nt][1] = *(u32*)(Bl + o + 16);
                }
                #pragma unroll
                for (int mt = 0; mt < 2; ++mt)
                    #pragma unroll
                    for (int nt = 0; nt < 4; ++nt) {
                        mma16816(acc[p][mt][nt], ah[mt], bh[nt]);
                        mma16816(acc[p][mt][nt], ah[mt], bl[nt]);
                        mma16816(acc[p][mt][nt], al[mt], bh[nt]);
                    }
            }
        }

        if (t + 1 < NTIL) store_smem(buf ^ 1);
        __syncthreads();
    }

    // ---- epilogue: re = P1-P2, im = P3-P1-P2, soft-threshold, store ----
    #pragma unroll
    for (int mt = 0; mt < 2; ++mt) {
        #pragma unroll
        for (int nt = 0; nt < 4; ++nt) {
            #pragma unroll
            for (int half = 0; half < 2; ++half) {   // half 0: c0,c1 ; half 1: c2,c3
                const int q0 = half * 2;
                const int row = row0 + wm + mt * 16 + r4 + half * 8;
                const int col = col0 + wn + nt * 8 + c2;
                float p1a = acc[0][mt][nt][q0],     p1b = acc[0][mt][nt][q0 + 1];
                float p2a = acc[1][mt][nt][q0],     p2b = acc[1][mt][nt][q0 + 1];
                float p3a = acc[2][mt][nt][q0],     p3b = acc[2][mt][nt][q0 + 1];
                float rea = p1a - p2a,  reb = p1b - p2b;
                float ima = p3a - p1a - p2a, imb = p3b - p1b - p2b;
                float maga = sqrtf(rea * rea + ima * ima);
                float sca  = fmaxf(maga - BETA, 0.0f) / fmaxf(maga, EPSL);
                float magb = sqrtf(reb * reb + imb * imb);
                float scb  = fmaxf(magb - BETA, 0.0f) / fmaxf(magb, EPSL);
                rea *= sca; ima *= sca; reb *= scb; imb *= scb;
                const int e = row * Bb + col;
                if (omode == 0) {
                    __nv_bfloat162 pa = __floats2bfloat162_rn(rea, ima);
                    __nv_bfloat162 pb = __floats2bfloat162_rn(reb, imb);
                    u32 ua, ub; memcpy(&ua, &pa, 4); memcpy(&ub, &pb, 4);
                    uint2 w = make_uint2(ua, ub);
                    *(uint2*)((u32*)out + e) = w;
                } else {
                    float2 w = make_float2(rea, reb);
                    *(float2*)((float*)out + e) = w;
                }
            }
        }
    }
}

extern "C" void kernel_launch(void* const* d_in, const int* in_sizes, int n_in,
                              void* d_out, int out_size) {
    // Crash-proof input dispatch: classify by element count (elements or bytes).
    int scale = 1;
    bool have2047 = false, have8188 = false;
    for (int i = 0; i < n_in && i < 8; ++i) {
        if (in_sizes[i] == 2 * Nn - 1) have2047 = true;
        if (in_sizes[i] == (2 * Nn - 1) * 4) have8188 = true;
    }
    if (!have2047 && have8188) scale = 4;

    const float* vp[2] = {0, 0};
    const float* xp[2] = {0, 0};
    const float* mp[4] = {0, 0, 0, 0};
    int nv = 0, nx = 0, nm = 0;
    for (int i = 0; i < n_in && i < 8; ++i) {
        const float* p = (const float*)d_in[i];
        long s = in_sizes[i];
        if (s == (long)(2 * Nn - 1) * scale)      { if (nv < 2) vp[nv++] = p; }
        else if (s == (long)Nn * Bb * scale)      { if (nx < 2) xp[nx++] = p; }
        else if (s == (long)Nn * Mm * scale)      { if (nm < 4) mp[nm++] = p; }
    }
    const float* v_re  = vp[0] ? vp[0] : (const float*)d_in[0];
    const float* v_im  = vp[1] ? vp[1] : (const float*)d_in[1];
    const float* W2_re = mp[0] ? mp[0] : (const float*)d_in[2];
    const float* W2_im = mp[1] ? mp[1] : (const float*)d_in[3];
    const float* x_re  = xp[0] ? xp[0] : (const float*)d_in[4];
    const float* x_im  = xp[1] ? xp[1] : (const float*)d_in[5];
    const float* y_re  = mp[2] ? mp[2] : (const float*)d_in[6];
    const float* y_im  = mp[3] ? mp[3] : (const float*)d_in[7];

    const int omode = (out_size >= 2 * Nn * Bb) ? 0 : 1;

    cudaFuncSetAttribute(toeplitz_hmma_kernel,
                         cudaFuncAttributeMaxDynamicSharedMemorySize, SMTOT);
    dim3 grid(Bb / TNt, Nn / TMt);   // (16, 8) = 128 CTAs
    dim3 block(THREADS);
    toeplitz_hmma_kernel<<<grid, block, SMTOT>>>(
        v_re, v_im, W2_re, W2_im, x_re, x_im, y_re, y_im,
        d_out, omode);
}